// round 15
// baseline (speedup 1.0000x reference)
#include <cuda_runtime.h>
#include <cuda_fp16.h>
#include <cstdint>

#define H 1024
#define B 32
#define S 2048
#define M_TOTAL (B*S)

// GEMM tiling (fp16 operands, fp32 accum), swizzled SW128 images
#define BM 128
#define BN 128
#define BK 64                  // K halves per stage = 128B row
#define KS2 16                 // stages = H/BK
#define MT (M_TOTAL/BM)        // 512
#define NT (H/BN)              // 8
#define A_TILE_HALFS (BM*BK)   // 8192 -> 16384 B
#define B_TILE_HALFS (BN*BK)
#define A_TILE_BYTES (A_TILE_HALFS*2)
#define B_TILE_BYTES (B_TILE_HALFS*2)
#define STAGE_BYTES  (A_TILE_BYTES + B_TILE_BYTES)   // 32768
#define NSTAGES 3
#define DSMEM_BYTES (NSTAGES*STAGE_BYTES)            // 98304 (2 CTAs/SM)

#define SW128(off) ((off) ^ (((off) >> 3) & 0x70))

// prep fusion block ranges
#define PREP_B_BLOCKS   (NT*KS2)          // 128 (stageB)
#define PREP_C_BLOCKS   512               // cbias
#define PREP_A_BLOCKS   (MT*KS2)          // 8192 (stageA)
#define PREP_TOTAL      (PREP_B_BLOCKS + PREP_C_BLOCKS + PREP_A_BLOCKS)

// ---------------- device-global scratch ----------------
__device__ float g_part[NT*M_TOTAL];
__device__ float g_cbias[B*H];
__device__ __align__(128) __half g_Ah[(size_t)MT*KS2*A_TILE_HALFS];  // 128 MB
__device__ __align__(128) __half g_Bh[(size_t)NT*KS2*B_TILE_HALFS];  // 2 MB

// ---------------- helpers ----------------
__device__ __forceinline__ float tanh_fast(float x){
    float y; asm("tanh.approx.f32 %0, %1;" : "=f"(y) : "f"(x)); return y;
}
__device__ __forceinline__ uint32_t smem_u32(const void* p){
    uint32_t a;
    asm("{ .reg .u64 t; cvta.to.shared.u64 t, %1; cvt.u32.u64 %0, t; }" : "=r"(a) : "l"(p));
    return a;
}
#define MBARRIER_INIT(addr, cnt) \
    asm volatile("mbarrier.init.shared.b64 [%0], %1;" :: "r"((uint32_t)(addr)), "r"((uint32_t)(cnt)) : "memory")
#define MBARRIER_EXPECT_TX(addr, tx) \
    asm volatile("mbarrier.arrive.expect_tx.shared.b64 _, [%0], %1;" \
                 :: "r"((uint32_t)(addr)), "r"((uint32_t)(tx)) : "memory")
#define MBARRIER_WAIT_PARITY(addr, ph) do { \
    uint32_t _m = (uint32_t)(addr), _p = (uint32_t)(ph), _d; \
    asm volatile("{\n\t.reg .pred p;\n\t" \
        "mbarrier.try_wait.parity.acquire.cta.shared::cta.b64 p, [%1], %2;\n\t" \
        "selp.b32 %0, 1, 0, p;\n\t}" : "=r"(_d) : "r"(_m), "r"(_p) : "memory"); \
    if (!_d) { \
        asm volatile("{\n\t.reg .pred P1;\n\t" \
            "WL_%=:\n\t" \
            "mbarrier.try_wait.parity.acquire.cta.shared::cta.b64 P1, [%0], %1, 0x989680;\n\t" \
            "@P1 bra.uni WD_%=;\n\t" \
            "bra.uni WL_%=;\n\t" \
            "WD_%=:\n\t}" :: "r"(_m), "r"(_p) : "memory"); \
    } \
} while(0)

__device__ __forceinline__ void bulk_g2s(uint32_t dst, const void* src,
                                         uint32_t bytes, uint32_t mbar){
    asm volatile(
        "cp.async.bulk.shared::cluster.global.mbarrier::complete_tx::bytes "
        "[%0], [%1], %2, [%3];"
        :: "r"(dst), "l"(src), "r"(bytes), "r"(mbar) : "memory");
}
__device__ __forceinline__ void ldmx4(uint32_t* r, uint32_t addr){
    asm volatile("ldmatrix.sync.aligned.m8n8.x4.shared.b16 {%0,%1,%2,%3}, [%4];"
        : "=r"(r[0]), "=r"(r[1]), "=r"(r[2]), "=r"(r[3]) : "r"(addr));
}
__device__ __forceinline__ void mma16816(float* d, const uint32_t* a,
                                         uint32_t b0, uint32_t b1){
    asm volatile(
        "mma.sync.aligned.m16n8k16.row.col.f32.f16.f16.f32 "
        "{%0,%1,%2,%3}, {%4,%5,%6,%7}, {%8,%9}, {%0,%1,%2,%3};"
        : "+f"(d[0]), "+f"(d[1]), "+f"(d[2]), "+f"(d[3])
        : "r"(a[0]), "r"(a[1]), "r"(a[2]), "r"(a[3]), "r"(b0), "r"(b1));
}

// ============================================================
// Fused prep: stageB (blocks 0..127) | cbias (128..639)
//             | stageA (640..8831)  — all independent
// ============================================================
__device__ __forceinline__ void do_stage_tile(const float* __restrict__ src0,
                                              int srcStride, __half* __restrict__ tileH,
                                              int t){
    int row = t >> 1;
    int hoff = (t & 1) * 32;
    const float4* src = reinterpret_cast<const float4*>(
        src0 + (size_t)row*srcStride + hoff);
    __half hbuf[32];
    #pragma unroll
    for (int i = 0; i < 8; i++){
        float4 v = src[i];
        hbuf[i*4+0] = __float2half_rn(v.x); hbuf[i*4+1] = __float2half_rn(v.y);
        hbuf[i*4+2] = __float2half_rn(v.z); hbuf[i*4+3] = __float2half_rn(v.w);
    }
    char* tileBase = reinterpret_cast<char*>(tileH);
    const uint4* hb = reinterpret_cast<const uint4*>(hbuf);
    uint32_t off0 = (uint32_t)(row*128 + hoff*2);
    #pragma unroll
    for (int j = 0; j < 4; j++){
        uint32_t off = off0 + j*16;
        *reinterpret_cast<uint4*>(tileBase + SW128(off)) = hb[j];
    }
}

__global__ void prep_kernel(const float* __restrict__ past,
                            const float* __restrict__ Wproj,
                            const float* __restrict__ current,
                            const float* __restrict__ bproj){
    int bid = blockIdx.x;
    int t = threadIdx.x;

    if (bid < PREP_B_BLOCKS){
        int ks = bid & 15;
        int nt = bid >> 4;
        do_stage_tile(Wproj + (size_t)(nt*BN)*2048 + ks*BK, 2048,
                      &g_Bh[(size_t)(nt*KS2 + ks)*B_TILE_HALFS], t);
        return;
    }
    bid -= PREP_B_BLOCKS;
    if (bid < PREP_C_BLOCKS){
        int lane = t & 31, wid = t >> 5;
        int h = (bid & 127) * 8 + wid;
        int b0 = (bid >> 7) * 8;
        const float4* wr = reinterpret_cast<const float4*>(Wproj + (size_t)h*2048 + H);
        float4 w[8];
        #pragma unroll
        for (int i = 0; i < 8; i++) w[i] = wr[i*32 + lane];
        float bp = bproj[h];
        #pragma unroll
        for (int bb = 0; bb < 8; bb++){
            int b = b0 + bb;
            const float4* cr = reinterpret_cast<const float4*>(current + b*H);
            float p = 0.f;
            #pragma unroll
            for (int i = 0; i < 8; i++){
                float4 c = cr[i*32 + lane];
                p += c.x*w[i].x + c.y*w[i].y + c.z*w[i].z + c.w*w[i].w;
            }
            #pragma unroll
            for (int o = 16; o; o >>= 1) p += __shfl_xor_sync(0xffffffffu, p, o);
            if (lane == 0) g_cbias[b*H + h] = p + bp;
        }
        return;
    }
    bid -= PREP_C_BLOCKS;
    {
        int ks = bid & 15;
        int mt = bid >> 4;
        do_stage_tile(past + (size_t)(mt*BM)*H + ks*BK, H,
                      &g_Ah[(size_t)(mt*KS2 + ks)*A_TILE_HALFS], t);
    }
}

// ============================================================
// GEMM: fp16 mma.sync, 128x128 tile, 2 CTAs/SM, bulk pipeline,
//       fused tanh/score epilogue (proven version, unchanged)
// ============================================================
__global__ void __launch_bounds__(256, 2) gemm_score(
    const float* __restrict__ wscore)
{
    extern __shared__ __align__(128) char dsm[];
    __shared__ uint64_t full[NSTAGES];
    __shared__ float cbS[BN];
    __shared__ float wsS[BN];
    __shared__ float sred[2][BM];

    const int tid = threadIdx.x, wid = tid >> 5, lane = tid & 31;
    const int ntIdx = blockIdx.x, mtIdx = blockIdx.y;
    const int mTile = mtIdx * BM;
    const int nTile = ntIdx * BN;
    const int b = mTile >> 11;
    const uint32_t smemBase = smem_u32(dsm);

    if (tid == 0){
        #pragma unroll
        for (int s = 0; s < NSTAGES; s++) MBARRIER_INIT(smem_u32(&full[s]), 1);
    }
    if (tid < BN){
        cbS[tid] = g_cbias[b*H + nTile + tid];
        wsS[tid] = wscore[nTile + tid];
    }
    __syncthreads();

    if (tid == 0){
        #pragma unroll
        for (int s = 0; s < NSTAGES; s++){
            uint32_t mb = smem_u32(&full[s]);
            MBARRIER_EXPECT_TX(mb, STAGE_BYTES);
            bulk_g2s(smemBase + s*STAGE_BYTES,
                     &g_Ah[(size_t)(mtIdx*KS2 + s)*A_TILE_HALFS], A_TILE_BYTES, mb);
        }
    } else if (tid == 32){
        #pragma unroll
        for (int s = 0; s < NSTAGES; s++){
            bulk_g2s(smemBase + s*STAGE_BYTES + A_TILE_BYTES,
                     &g_Bh[(size_t)(ntIdx*KS2 + s)*B_TILE_HALFS], B_TILE_BYTES,
                     smem_u32(&full[s]));
        }
    }

    const int warpM = wid & 3;
    const int warpN = wid >> 2;
    const int qr = lane >> 2, qc = lane & 3;

    const uint32_t aRowLane = (uint32_t)(lane & 15);
    const uint32_t aColLane = (uint32_t)((lane >> 4) * 16);
    const uint32_t bRowLane = (uint32_t)(((lane >> 4) << 3) + (lane & 7));
    const uint32_t bColLane = (uint32_t)(((lane >> 3) & 1) * 16);

    float acc[2][8][4];
    #pragma unroll
    for (int i = 0; i < 2; i++)
        #pragma unroll
        for (int j = 0; j < 8; j++)
            #pragma unroll
            for (int k = 0; k < 4; k++) acc[i][j][k] = 0.f;

    int slot = 0, ph = 0;
    #pragma unroll 1
    for (int s = 0; s < KS2; s++){
        MBARRIER_WAIT_PARITY(smem_u32(&full[slot]), ph);
        const uint32_t aB = smemBase + (uint32_t)slot*STAGE_BYTES;
        const uint32_t bB = aB + A_TILE_BYTES;

        #pragma unroll
        for (int J = 0; J < 4; J++){
            uint32_t a[2][4], bq[4][4];
            #pragma unroll
            for (int mf = 0; mf < 2; mf++){
                uint32_t off = (uint32_t)(warpM*32 + mf*16 + aRowLane)*128u
                             + (uint32_t)J*32u + aColLane;
                ldmx4(a[mf], aB + SW128(off));
            }
            #pragma unroll
            for (int np = 0; np < 4; np++){
                uint32_t off = (uint32_t)(warpN*64 + np*16 + bRowLane)*128u
                             + (uint32_t)J*32u + bColLane;
                ldmx4(bq[np], bB + SW128(off));
            }
            #pragma unroll
            for (int np = 0; np < 4; np++){
                #pragma unroll
                for (int hh = 0; hh < 2; hh++){
                    int nf = np*2 + hh;
                    #pragma unroll
                    for (int mf = 0; mf < 2; mf++)
                        mma16816(acc[mf][nf], a[mf], bq[np][hh*2], bq[np][hh*2+1]);
                }
            }
        }
        __syncthreads();
        if (s + NSTAGES < KS2){
            int ns = s + NSTAGES;
            uint32_t mb = smem_u32(&full[slot]);
            if (tid == 0){
                MBARRIER_EXPECT_TX(mb, STAGE_BYTES);
                bulk_g2s(smemBase + (uint32_t)slot*STAGE_BYTES,
                         &g_Ah[(size_t)(mtIdx*KS2 + ns)*A_TILE_HALFS],
                         A_TILE_BYTES, mb);
            } else if (tid == 32){
                bulk_g2s(smemBase + (uint32_t)slot*STAGE_BYTES + A_TILE_BYTES,
                         &g_Bh[(size_t)(ntIdx*KS2 + ns)*B_TILE_HALFS],
                         B_TILE_BYTES, mb);
            }
        }
        if (++slot == NSTAGES){ slot = 0; ph ^= 1; }
    }

    #pragma unroll
    for (int mf = 0; mf < 2; mf++){
        #pragma unroll
        for (int rr = 0; rr < 2; rr++){
            float p = 0.f;
            #pragma unroll
            for (int nf = 0; nf < 8; nf++){
                int c0 = warpN*64 + nf*8 + qc*2;
                p += tanh_fast(acc[mf][nf][rr*2+0] + cbS[c0    ]) * wsS[c0    ];
                p += tanh_fast(acc[mf][nf][rr*2+1] + cbS[c0 + 1]) * wsS[c0 + 1];
            }
            p += __shfl_xor_sync(0xffffffffu, p, 1);
            p += __shfl_xor_sync(0xffffffffu, p, 2);
            if (qc == 0){
                int rloc = warpM*32 + mf*16 + rr*8 + qr;
                sred[warpN][rloc] = p;
            }
        }
    }
    __syncthreads();
    if (tid < BM){
        g_part[(size_t)ntIdx*M_TOTAL + mTile + tid] = sred[0][tid] + sred[1][tid];
    }
}

// ============================================================
// softmax over S per batch (sums NT=8 partials) + zero outAtt
// ============================================================
__global__ void softmax_kernel(float* __restrict__ attn,
                               float* __restrict__ outAtt){
    __shared__ float red[256];
    int bidx = blockIdx.x, tid = threadIdx.x;

    float4 z = make_float4(0.f,0.f,0.f,0.f);
    reinterpret_cast<float4*>(outAtt + bidx*H)[tid] = z;

    const size_t base = (size_t)bidx*S;
    float m = -1e30f;
    float sc[8];
    #pragma unroll
    for (int j = 0; j < 8; j++){
        size_t i = base + tid + j*256;
        float v = 0.f;
        #pragma unroll
        for (int k = 0; k < NT; k++) v += g_part[(size_t)k*M_TOTAL + i];
        sc[j] = v;
        m = fmaxf(m, v);
    }
    red[tid] = m; __syncthreads();
    for (int o = 128; o; o >>= 1){ if (tid < o) red[tid] = fmaxf(red[tid], red[tid+o]); __syncthreads(); }
    m = red[0]; __syncthreads();
    float sum = 0.f;
    float* a = attn + base;
    #pragma unroll
    for (int j = 0; j < 8; j++){
        float e = __expf(sc[j] - m);
        a[tid + j*256] = e;
        sum += e;
    }
    red[tid] = sum; __syncthreads();
    for (int o = 128; o; o >>= 1){ if (tid < o) red[tid] += red[tid+o]; __syncthreads(); }
    float inv = 1.f / red[0];
    #pragma unroll
    for (int j = 0; j < 8; j++) a[tid + j*256] *= inv;
}

// ============================================================
// attend v3: 1024 blocks (64 s-rows each), high residency
//   grid (32, 32), block 256; thread = (hgrp 0..127, half 0..1)
// ============================================================
__global__ void attend_kernel(const float* __restrict__ attn,
                              float* __restrict__ outAtt){
    __shared__ float w[64];
    __shared__ float sred[128][8];
    int bidx = blockIdx.y, ch = blockIdx.x, tid = threadIdx.x;
    int s0 = ch * 64;
    if (tid < 64) w[tid] = attn[bidx*S + s0 + tid];
    __syncthreads();

    const int hgrp = tid & 127;          // h = hgrp*8 .. +7
    const int half = tid >> 7;           // 0..1: 32-row halves
    const int ks   = hgrp >> 3;          // K-tile index (BK=64 halves)
    const uint32_t chunkOff = (uint32_t)(hgrp & 7) * 16u;

    const int tile = (bidx*S + s0) >> 7;       // A-tile
    const int rbase = (s0 & 127) + half*32;    // row within tile
    const char* tileBase = reinterpret_cast<const char*>(
        &g_Ah[(size_t)(tile*KS2 + ks)*A_TILE_HALFS]);
    const float* wloc = &w[half*32];

    float f[8];
    #pragma unroll
    for (int k = 0; k < 8; k++) f[k] = 0.f;

    #pragma unroll 8
    for (int i = 0; i < 32; i++){
        uint32_t off = (uint32_t)(rbase + i)*128u + chunkOff;
        uint4 v = *reinterpret_cast<const uint4*>(tileBase + SW128(off));
        float ws = wloc[i];
        float2 p0 = __half22float2(*reinterpret_cast<__half2*>(&v.x));
        float2 p1 = __half22float2(*reinterpret_cast<__half2*>(&v.y));
        float2 p2 = __half22float2(*reinterpret_cast<__half2*>(&v.z));
        float2 p3 = __half22float2(*reinterpret_cast<__half2*>(&v.w));
        f[0] += ws*p0.x; f[1] += ws*p0.y;
        f[2] += ws*p1.x; f[3] += ws*p1.y;
        f[4] += ws*p2.x; f[5] += ws*p2.y;
        f[6] += ws*p3.x; f[7] += ws*p3.y;
    }

    if (half == 1){
        #pragma unroll
        for (int k = 0; k < 8; k++) sred[hgrp][k] = f[k];
    }
    __syncthreads();
    if (half == 0){
        float* o = outAtt + bidx*H + hgrp*8;
        #pragma unroll
        for (int k = 0; k < 8; k++)
            atomicAdd(o + k, f[k] + sred[hgrp][k]);
    }
}

// ============================================================
extern "C" void kernel_launch(void* const* d_in, const int* in_sizes, int n_in,
                              void* d_out, int out_size)
{
    const float* current = (const float*)d_in[0];
    const float* past    = (const float*)d_in[1];
    const float* Wproj   = (const float*)d_in[2];
    const float* bproj   = (const float*)d_in[3];
    const float* wscore  = (const float*)d_in[4];

    float* outAtt  = (float*)d_out;
    float* outAttn = (float*)d_out + B*H;

    static int smem_set = 0;
    if (!smem_set){
        cudaFuncSetAttribute(gemm_score,
                             cudaFuncAttributeMaxDynamicSharedMemorySize, DSMEM_BYTES);
        smem_set = 1;
    }

    prep_kernel   <<<PREP_TOTAL, 256>>>(past, Wproj, current, bproj);  // 1
    gemm_score    <<<dim3(NT, MT), 256, DSMEM_BYTES>>>(wscore);        // 2
    softmax_kernel<<<B, 256>>>(outAttn, outAtt);                       // 3
    attend_kernel <<<dim3(S/64, B), 256>>>(outAttn, outAtt);           // 4 <- profiled
}

// round 16
// speedup vs baseline: 1.0089x; 1.0089x over previous
#include <cuda_runtime.h>
#include <cuda_fp16.h>
#include <cstdint>

#define H 1024
#define B 32
#define S 2048
#define M_TOTAL (B*S)

// GEMM tiling (fp16 operands, fp32 accum), swizzled SW128 images
#define BM 128
#define BN 128
#define BK 64                  // K halves per stage = 128B row
#define KS2 16                 // stages = H/BK
#define MT (M_TOTAL/BM)        // 512
#define NT (H/BN)              // 8
#define A_TILE_HALFS (BM*BK)   // 8192 -> 16384 B
#define B_TILE_HALFS (BN*BK)
#define A_TILE_BYTES (A_TILE_HALFS*2)
#define B_TILE_BYTES (B_TILE_HALFS*2)
#define STAGE_BYTES  (A_TILE_BYTES + B_TILE_BYTES)   // 32768
#define NSTAGES 3
#define DSMEM_BYTES (NSTAGES*STAGE_BYTES)            // 98304 (2 CTAs/SM)

#define SW128(off) ((off) ^ (((off) >> 3) & 0x70))

// prep fusion block ranges
#define PREP_B_BLOCKS   (NT*KS2)          // 128 (stageB)
#define PREP_C_BLOCKS   512               // cbias
#define PREP_A_BLOCKS   (MT*KS2)          // 8192 (stageA)
#define PREP_TOTAL      (PREP_B_BLOCKS + PREP_C_BLOCKS + PREP_A_BLOCKS)

// ---------------- device-global scratch ----------------
__device__ float g_part[NT*M_TOTAL];
__device__ float g_cbias[B*H];
__device__ __align__(128) __half g_Ah[(size_t)MT*KS2*A_TILE_HALFS];  // 128 MB
__device__ __align__(128) __half g_Bh[(size_t)NT*KS2*B_TILE_HALFS];  // 2 MB

// ---------------- helpers ----------------
__device__ __forceinline__ float tanh_fast(float x){
    float y; asm("tanh.approx.f32 %0, %1;" : "=f"(y) : "f"(x)); return y;
}
__device__ __forceinline__ uint32_t smem_u32(const void* p){
    uint32_t a;
    asm("{ .reg .u64 t; cvta.to.shared.u64 t, %1; cvt.u32.u64 %0, t; }" : "=r"(a) : "l"(p));
    return a;
}
#define MBARRIER_INIT(addr, cnt) \
    asm volatile("mbarrier.init.shared.b64 [%0], %1;" :: "r"((uint32_t)(addr)), "r"((uint32_t)(cnt)) : "memory")
#define MBARRIER_EXPECT_TX(addr, tx) \
    asm volatile("mbarrier.arrive.expect_tx.shared.b64 _, [%0], %1;" \
                 :: "r"((uint32_t)(addr)), "r"((uint32_t)(tx)) : "memory")
#define MBARRIER_WAIT_PARITY(addr, ph) do { \
    uint32_t _m = (uint32_t)(addr), _p = (uint32_t)(ph), _d; \
    asm volatile("{\n\t.reg .pred p;\n\t" \
        "mbarrier.try_wait.parity.acquire.cta.shared::cta.b64 p, [%1], %2;\n\t" \
        "selp.b32 %0, 1, 0, p;\n\t}" : "=r"(_d) : "r"(_m), "r"(_p) : "memory"); \
    if (!_d) { \
        asm volatile("{\n\t.reg .pred P1;\n\t" \
            "WL_%=:\n\t" \
            "mbarrier.try_wait.parity.acquire.cta.shared::cta.b64 P1, [%0], %1, 0x989680;\n\t" \
            "@P1 bra.uni WD_%=;\n\t" \
            "bra.uni WL_%=;\n\t" \
            "WD_%=:\n\t}" :: "r"(_m), "r"(_p) : "memory"); \
    } \
} while(0)

__device__ __forceinline__ void bulk_g2s(uint32_t dst, const void* src,
                                         uint32_t bytes, uint32_t mbar){
    asm volatile(
        "cp.async.bulk.shared::cluster.global.mbarrier::complete_tx::bytes "
        "[%0], [%1], %2, [%3];"
        :: "r"(dst), "l"(src), "r"(bytes), "r"(mbar) : "memory");
}
__device__ __forceinline__ void ldmx4(uint32_t* r, uint32_t addr){
    asm volatile("ldmatrix.sync.aligned.m8n8.x4.shared.b16 {%0,%1,%2,%3}, [%4];"
        : "=r"(r[0]), "=r"(r[1]), "=r"(r[2]), "=r"(r[3]) : "r"(addr));
}
__device__ __forceinline__ void mma16816(float* d, const uint32_t* a,
                                         uint32_t b0, uint32_t b1){
    asm volatile(
        "mma.sync.aligned.m16n8k16.row.col.f32.f16.f16.f32 "
        "{%0,%1,%2,%3}, {%4,%5,%6,%7}, {%8,%9}, {%0,%1,%2,%3};"
        : "+f"(d[0]), "+f"(d[1]), "+f"(d[2]), "+f"(d[3])
        : "r"(a[0]), "r"(a[1]), "r"(a[2]), "r"(a[3]), "r"(b0), "r"(b1));
}

// ============================================================
// Fused prep: stageB (blocks 0..127) | cbias (128..639)
//             | stageA (640..8831)  — all independent
// ============================================================
__device__ __forceinline__ void do_stage_tile(const float* __restrict__ src0,
                                              int srcStride, __half* __restrict__ tileH,
                                              int t){
    int row = t >> 1;
    int hoff = (t & 1) * 32;
    const float4* src = reinterpret_cast<const float4*>(
        src0 + (size_t)row*srcStride + hoff);
    __half hbuf[32];
    #pragma unroll
    for (int i = 0; i < 8; i++){
        float4 v = src[i];
        hbuf[i*4+0] = __float2half_rn(v.x); hbuf[i*4+1] = __float2half_rn(v.y);
        hbuf[i*4+2] = __float2half_rn(v.z); hbuf[i*4+3] = __float2half_rn(v.w);
    }
    char* tileBase = reinterpret_cast<char*>(tileH);
    const uint4* hb = reinterpret_cast<const uint4*>(hbuf);
    uint32_t off0 = (uint32_t)(row*128 + hoff*2);
    #pragma unroll
    for (int j = 0; j < 4; j++){
        uint32_t off = off0 + j*16;
        *reinterpret_cast<uint4*>(tileBase + SW128(off)) = hb[j];
    }
}

__global__ void prep_kernel(const float* __restrict__ past,
                            const float* __restrict__ Wproj,
                            const float* __restrict__ current,
                            const float* __restrict__ bproj){
    int bid = blockIdx.x;
    int t = threadIdx.x;

    if (bid < PREP_B_BLOCKS){
        int ks = bid & 15;
        int nt = bid >> 4;
        do_stage_tile(Wproj + (size_t)(nt*BN)*2048 + ks*BK, 2048,
                      &g_Bh[(size_t)(nt*KS2 + ks)*B_TILE_HALFS], t);
        return;
    }
    bid -= PREP_B_BLOCKS;
    if (bid < PREP_C_BLOCKS){
        int lane = t & 31, wid = t >> 5;
        int h = (bid & 127) * 8 + wid;
        int b0 = (bid >> 7) * 8;
        const float4* wr = reinterpret_cast<const float4*>(Wproj + (size_t)h*2048 + H);
        float4 w[8];
        #pragma unroll
        for (int i = 0; i < 8; i++) w[i] = wr[i*32 + lane];
        float bp = bproj[h];
        #pragma unroll
        for (int bb = 0; bb < 8; bb++){
            int b = b0 + bb;
            const float4* cr = reinterpret_cast<const float4*>(current + b*H);
            float p = 0.f;
            #pragma unroll
            for (int i = 0; i < 8; i++){
                float4 c = cr[i*32 + lane];
                p += c.x*w[i].x + c.y*w[i].y + c.z*w[i].z + c.w*w[i].w;
            }
            #pragma unroll
            for (int o = 16; o; o >>= 1) p += __shfl_xor_sync(0xffffffffu, p, o);
            if (lane == 0) g_cbias[b*H + h] = p + bp;
        }
        return;
    }
    bid -= PREP_C_BLOCKS;
    {
        int ks = bid & 15;
        int mt = bid >> 4;
        do_stage_tile(past + (size_t)(mt*BM)*H + ks*BK, H,
                      &g_Ah[(size_t)(mt*KS2 + ks)*A_TILE_HALFS], t);
    }
}

// ============================================================
// GEMM: fp16 mma.sync, 128x128 tile, 2 CTAs/SM, bulk pipeline,
//       fused tanh/score epilogue (proven version, unchanged)
// ============================================================
__global__ void __launch_bounds__(256, 2) gemm_score(
    const float* __restrict__ wscore)
{
    extern __shared__ __align__(128) char dsm[];
    __shared__ uint64_t full[NSTAGES];
    __shared__ float cbS[BN];
    __shared__ float wsS[BN];
    __shared__ float sred[2][BM];

    const int tid = threadIdx.x, wid = tid >> 5, lane = tid & 31;
    const int ntIdx = blockIdx.x, mtIdx = blockIdx.y;
    const int mTile = mtIdx * BM;
    const int nTile = ntIdx * BN;
    const int b = mTile >> 11;
    const uint32_t smemBase = smem_u32(dsm);

    if (tid == 0){
        #pragma unroll
        for (int s = 0; s < NSTAGES; s++) MBARRIER_INIT(smem_u32(&full[s]), 1);
    }
    if (tid < BN){
        cbS[tid] = g_cbias[b*H + nTile + tid];
        wsS[tid] = wscore[nTile + tid];
    }
    __syncthreads();

    if (tid == 0){
        #pragma unroll
        for (int s = 0; s < NSTAGES; s++){
            uint32_t mb = smem_u32(&full[s]);
            MBARRIER_EXPECT_TX(mb, STAGE_BYTES);
            bulk_g2s(smemBase + s*STAGE_BYTES,
                     &g_Ah[(size_t)(mtIdx*KS2 + s)*A_TILE_HALFS], A_TILE_BYTES, mb);
        }
    } else if (tid == 32){
        #pragma unroll
        for (int s = 0; s < NSTAGES; s++){
            bulk_g2s(smemBase + s*STAGE_BYTES + A_TILE_BYTES,
                     &g_Bh[(size_t)(ntIdx*KS2 + s)*B_TILE_HALFS], B_TILE_BYTES,
                     smem_u32(&full[s]));
        }
    }

    const int warpM = wid & 3;
    const int warpN = wid >> 2;
    const int qr = lane >> 2, qc = lane & 3;

    const uint32_t aRowLane = (uint32_t)(lane & 15);
    const uint32_t aColLane = (uint32_t)((lane >> 4) * 16);
    const uint32_t bRowLane = (uint32_t)(((lane >> 4) << 3) + (lane & 7));
    const uint32_t bColLane = (uint32_t)(((lane >> 3) & 1) * 16);

    float acc[2][8][4];
    #pragma unroll
    for (int i = 0; i < 2; i++)
        #pragma unroll
        for (int j = 0; j < 8; j++)
            #pragma unroll
            for (int k = 0; k < 4; k++) acc[i][j][k] = 0.f;

    int slot = 0, ph = 0;
    #pragma unroll 1
    for (int s = 0; s < KS2; s++){
        MBARRIER_WAIT_PARITY(smem_u32(&full[slot]), ph);
        const uint32_t aB = smemBase + (uint32_t)slot*STAGE_BYTES;
        const uint32_t bB = aB + A_TILE_BYTES;

        #pragma unroll
        for (int J = 0; J < 4; J++){
            uint32_t a[2][4], bq[4][4];
            #pragma unroll
            for (int mf = 0; mf < 2; mf++){
                uint32_t off = (uint32_t)(warpM*32 + mf*16 + aRowLane)*128u
                             + (uint32_t)J*32u + aColLane;
                ldmx4(a[mf], aB + SW128(off));
            }
            #pragma unroll
            for (int np = 0; np < 4; np++){
                uint32_t off = (uint32_t)(warpN*64 + np*16 + bRowLane)*128u
                             + (uint32_t)J*32u + bColLane;
                ldmx4(bq[np], bB + SW128(off));
            }
            #pragma unroll
            for (int np = 0; np < 4; np++){
                #pragma unroll
                for (int hh = 0; hh < 2; hh++){
                    int nf = np*2 + hh;
                    #pragma unroll
                    for (int mf = 0; mf < 2; mf++)
                        mma16816(acc[mf][nf], a[mf], bq[np][hh*2], bq[np][hh*2+1]);
                }
            }
        }
        __syncthreads();
        if (s + NSTAGES < KS2){
            int ns = s + NSTAGES;
            uint32_t mb = smem_u32(&full[slot]);
            if (tid == 0){
                MBARRIER_EXPECT_TX(mb, STAGE_BYTES);
                bulk_g2s(smemBase + (uint32_t)slot*STAGE_BYTES,
                         &g_Ah[(size_t)(mtIdx*KS2 + ns)*A_TILE_HALFS],
                         A_TILE_BYTES, mb);
            } else if (tid == 32){
                bulk_g2s(smemBase + (uint32_t)slot*STAGE_BYTES + A_TILE_BYTES,
                         &g_Bh[(size_t)(ntIdx*KS2 + ns)*B_TILE_HALFS],
                         B_TILE_BYTES, mb);
            }
        }
        if (++slot == NSTAGES){ slot = 0; ph ^= 1; }
    }

    #pragma unroll
    for (int mf = 0; mf < 2; mf++){
        #pragma unroll
        for (int rr = 0; rr < 2; rr++){
            float p = 0.f;
            #pragma unroll
            for (int nf = 0; nf < 8; nf++){
                int c0 = warpN*64 + nf*8 + qc*2;
                p += tanh_fast(acc[mf][nf][rr*2+0] + cbS[c0    ]) * wsS[c0    ];
                p += tanh_fast(acc[mf][nf][rr*2+1] + cbS[c0 + 1]) * wsS[c0 + 1];
            }
            p += __shfl_xor_sync(0xffffffffu, p, 1);
            p += __shfl_xor_sync(0xffffffffu, p, 2);
            if (qc == 0){
                int rloc = warpM*32 + mf*16 + rr*8 + qr;
                sred[warpN][rloc] = p;
            }
        }
    }
    __syncthreads();
    if (tid < BM){
        g_part[(size_t)ntIdx*M_TOTAL + mTile + tid] = sred[0][tid] + sred[1][tid];
    }
}

// ============================================================
// softmax over S per batch (sums NT=8 partials) + zero outAtt
// ============================================================
__global__ void softmax_kernel(float* __restrict__ attn,
                               float* __restrict__ outAtt){
    __shared__ float red[256];
    int bidx = blockIdx.x, tid = threadIdx.x;

    float4 z = make_float4(0.f,0.f,0.f,0.f);
    reinterpret_cast<float4*>(outAtt + bidx*H)[tid] = z;

    const size_t base = (size_t)bidx*S;
    float m = -1e30f;
    float sc[8];
    #pragma unroll
    for (int j = 0; j < 8; j++){
        size_t i = base + tid + j*256;
        float v = 0.f;
        #pragma unroll
        for (int k = 0; k < NT; k++) v += g_part[(size_t)k*M_TOTAL + i];
        sc[j] = v;
        m = fmaxf(m, v);
    }
    red[tid] = m; __syncthreads();
    for (int o = 128; o; o >>= 1){ if (tid < o) red[tid] = fmaxf(red[tid], red[tid+o]); __syncthreads(); }
    m = red[0]; __syncthreads();
    float sum = 0.f;
    float* a = attn + base;
    #pragma unroll
    for (int j = 0; j < 8; j++){
        float e = __expf(sc[j] - m);
        a[tid + j*256] = e;
        sum += e;
    }
    red[tid] = sum; __syncthreads();
    for (int o = 128; o; o >>= 1){ if (tid < o) red[tid] += red[tid+o]; __syncthreads(); }
    float inv = 1.f / red[0];
    #pragma unroll
    for (int j = 0; j < 8; j++) a[tid + j*256] *= inv;
}

// ============================================================
// attend v4: 512 blocks x 512 threads — one A-tile per block
//   (R14 atomic/tail count, R15 residency)
//   thread = (hgrp 0..127, quarter 0..3 of 32 rows)
// ============================================================
__global__ void __launch_bounds__(512) attend_kernel(
    const float* __restrict__ attn, float* __restrict__ outAtt){
    __shared__ float w[128];
    __shared__ float sred[3][128][8];
    int bidx = blockIdx.y, ch = blockIdx.x, tid = threadIdx.x;
    int s0 = ch * 128;
    if (tid < 128) w[tid] = attn[bidx*S + s0 + tid];
    __syncthreads();

    const int hgrp = tid & 127;          // h = hgrp*8 .. +7
    const int quad = tid >> 7;           // 0..3: 32-row quarters
    const int ks   = hgrp >> 3;          // K-tile index (BK=64 halves)
    const uint32_t chunkOff = (uint32_t)(hgrp & 7) * 16u;

    const int tile = (bidx*S + s0) >> 7; // one A-tile per block
    const char* tileBase = reinterpret_cast<const char*>(
        &g_Ah[(size_t)(tile*KS2 + ks)*A_TILE_HALFS]);
    const int r0 = quad * 32;
    const float* wloc = &w[r0];

    float f[8];
    #pragma unroll
    for (int k = 0; k < 8; k++) f[k] = 0.f;

    #pragma unroll 8
    for (int i = 0; i < 32; i++){
        uint32_t off = (uint32_t)(r0 + i)*128u + chunkOff;
        uint4 v = *reinterpret_cast<const uint4*>(tileBase + SW128(off));
        float ws = wloc[i];
        float2 p0 = __half22float2(*reinterpret_cast<__half2*>(&v.x));
        float2 p1 = __half22float2(*reinterpret_cast<__half2*>(&v.y));
        float2 p2 = __half22float2(*reinterpret_cast<__half2*>(&v.z));
        float2 p3 = __half22float2(*reinterpret_cast<__half2*>(&v.w));
        f[0] += ws*p0.x; f[1] += ws*p0.y;
        f[2] += ws*p1.x; f[3] += ws*p1.y;
        f[4] += ws*p2.x; f[5] += ws*p2.y;
        f[6] += ws*p3.x; f[7] += ws*p3.y;
    }

    if (quad > 0){
        #pragma unroll
        for (int k = 0; k < 8; k++) sred[quad-1][hgrp][k] = f[k];
    }
    __syncthreads();
    if (quad == 0){
        float* o = outAtt + bidx*H + hgrp*8;
        #pragma unroll
        for (int k = 0; k < 8; k++)
            atomicAdd(o + k, f[k] + sred[0][hgrp][k]
                             + sred[1][hgrp][k] + sred[2][hgrp][k]);
    }
}

// ============================================================
extern "C" void kernel_launch(void* const* d_in, const int* in_sizes, int n_in,
                              void* d_out, int out_size)
{
    const float* current = (const float*)d_in[0];
    const float* past    = (const float*)d_in[1];
    const float* Wproj   = (const float*)d_in[2];
    const float* bproj   = (const float*)d_in[3];
    const float* wscore  = (const float*)d_in[4];

    float* outAtt  = (float*)d_out;
    float* outAttn = (float*)d_out + B*H;

    static int smem_set = 0;
    if (!smem_set){
        cudaFuncSetAttribute(gemm_score,
                             cudaFuncAttributeMaxDynamicSharedMemorySize, DSMEM_BYTES);
        smem_set = 1;
    }

    prep_kernel   <<<PREP_TOTAL, 256>>>(past, Wproj, current, bproj);  // 1
    gemm_score    <<<dim3(NT, MT), 256, DSMEM_BYTES>>>(wscore);        // 2
    softmax_kernel<<<B, 256>>>(outAttn, outAtt);                       // 3
    attend_kernel <<<dim3(S/128, B), 512>>>(outAttn, outAtt);          // 4 <- profiled
}